// round 7
// baseline (speedup 1.0000x reference)
#include <cuda_runtime.h>

// VQ_86139864089353: per-dimension 1D vector quantization — SINGLE kernel.
// ze: (B, D, 1) f32 ; e: (K, D) f32.  out: [ z (B*D) f32 | zq (B*D) f32 ]
//
// Blocks 0..2 build per-dim sorted tables + LUT and release a flag; all
// blocks prefetch their ze data (overlapping the build), wait, load tables
// to smem, then do exact fp32 argmin over a 4-wide sorted window with the
// reference tie-break (min original index).

#define BN      262144
#define DDIM    3
#define KK      512
#define NBD     (BN * DDIM)
#define NEL     (BN * DDIM)
#define NCELL   2048
#define FLO     (-4.0f)
#define FW      (8.0f / (float)NCELL)    // 1/256 (dyadic)
#define FINVW   ((float)NCELL / 8.0f)    // 256   (dyadic)

#define MBLK    512
#define MVEC    2
#define MGRID   (NEL / (MBLK * MVEC))    // 768

__device__ float2         g_pair[DDIM][KK];    // {sorted value, (float)orig}
__device__ unsigned short g_lut[DDIM][NCELL];
__device__ int            g_ready;             // builders done counter (0 at rest)
__device__ int            g_done;              // finished-blocks counter (0 at rest)

// Monotone (order-preserving) uint32 map of an IEEE754 float.
__device__ __forceinline__ unsigned fkey(float f) {
    unsigned u = __float_as_uint(f);
    return u ^ ((unsigned)((int)u >> 31) | 0x80000000u);
}

__global__ void __launch_bounds__(MBLK, 4)
vq_all(const float2* __restrict__ ze2, const float* __restrict__ e,
       float* __restrict__ out) {
    __shared__ float2         s_pair[DDIM][KK];      // 12288 B
    __shared__ unsigned short s_lut[DDIM][NCELL];    // 12288 B

    const int tid = threadIdx.x;
    const int t   = blockIdx.x * MBLK + tid;         // float2 element index

    // Prefetch input early — overlaps the build phase below.
    float2 xv = ze2[t];

    // ---------------- builder blocks ----------------
    if (blockIdx.x < DDIM) {
        const int d = blockIdx.x;
        const int k = tid;                            // 0..511 (MBLK==512? no, 512 threads, k<512 ok)

        // smem scratch aliased onto the (not yet used) table arrays
        unsigned long long* s_k      = (unsigned long long*)s_pair;  // 4 KB
        float*              s_sorted = (float*)s_lut;                // 2 KB
        short*              s_org    = (short*)((char*)s_lut + 2048);

        const float v = e[k * DDIM + d];
        const unsigned long long kv =
            ((unsigned long long)fkey(v) << 16) | (unsigned)k;
        s_k[k] = kv;
        __syncthreads();

        // stable rank: key encodes (value, index) -> exact tie-break
        int r = 0;
#pragma unroll 8
        for (int j = 0; j < KK; ++j)
            r += (s_k[j] < kv);
        __syncthreads();                              // done reading s_k

        s_sorted[r] = v;
        s_org[r]    = (short)k;
        __syncthreads();

        g_pair[d][k] = make_float2(s_sorted[k], (float)s_org[k]);

        // LUT: conservative lower bound on insertion position (guard cell).
        for (int c = k; c < NCELL; c += KK) {
            float edge = FLO + (float)c * FW - FW;
            int lo = 0, hi = KK;
            while (lo < hi) {
                int m = (lo + hi) >> 1;
                if (s_sorted[m] < edge) lo = m + 1; else hi = m;
            }
            g_lut[d][c] = (unsigned short)lo;
        }

        __threadfence();                              // publish my writes to L2
        __syncthreads();                              // all threads published
        if (tid == 0) atomicAdd(&g_ready, 1);         // release
    }

    // ---------------- wait for tables ----------------
    if (tid == 0) {
        while (*(volatile int*)&g_ready != DDIM) __nanosleep(64);
        __threadfence();                              // acquire
    }
    __syncthreads();

    // load tables to smem (L2 path; builders' smem scratch is overwritten)
    {
        const float4* src = (const float4*)g_pair;
        float4*       dst = (float4*)s_pair;
        for (int i = tid; i < (int)(DDIM * KK * sizeof(float2) / 16); i += MBLK)
            dst[i] = __ldcg(src + i);
    }
    {
        const uint4* src = (const uint4*)g_lut;
        uint4*       dst = (uint4*)s_lut;
        for (int i = tid; i < (int)(DDIM * NCELL * sizeof(short) / 16); i += MBLK)
            dst[i] = __ldcg(src + i);
    }
    __syncthreads();

    // ---------------- main quantization ----------------
    const int n0 = t * MVEC;
    float xs[MVEC] = {xv.x, xv.y};
    float rz[MVEC], rq[MVEC];

    int d = n0 % 3;
#pragma unroll
    for (int j = 0; j < MVEC; ++j) {
        const float x = xs[j];

        float tt = fminf(fmaxf((x - FLO) * FINVW, 0.0f), (float)(NCELL - 1));
        int i = s_lut[d][(int)tt];
        while (i < KK && s_pair[d][i].x <= x) ++i;

        // exact fp32 argmin over sorted window [i-2, i+1], tie -> min orig
        float bestD = __int_as_float(0x7f800000);
        float bestO = 1.0e9f;
        float bestV = 0.0f;
#pragma unroll
        for (int off = -2; off <= 1; ++off) {
            int c = i + off;
            c = c < 0 ? 0 : (c > KK - 1 ? KK - 1 : c);
            float2 p = s_pair[d][c];
            float dx = x - p.x;
            float dd = dx * dx;                  // same fp32 op as reference
            bool take = (dd < bestD) || (dd == bestD && p.y < bestO);
            bestD = take ? dd : bestD;
            bestO = take ? p.y : bestO;
            bestV = take ? p.x : bestV;
        }
        rz[j] = bestO;
        rq[j] = bestV;

        d = (d == 2) ? 0 : d + 1;
    }

    ((float2*)out)[t]         = make_float2(rz[0], rz[1]);
    ((float2*)(out + NBD))[t] = make_float2(rq[0], rq[1]);

    // ---------------- self-clean for next graph replay ----------------
    __syncthreads();
    if (tid == 0) {
        if (atomicAdd(&g_done, 1) == MGRID - 1) {
            g_done  = 0;
            g_ready = 0;
        }
    }
}

// ---------------------------------------------------------------------------
extern "C" void kernel_launch(void* const* d_in, const int* in_sizes, int n_in,
                              void* d_out, int out_size) {
    const float* ze = (const float*)d_in[0];   // (B, D, 1)
    const float* e  = (const float*)d_in[1];   // (K, D)
    float* out = (float*)d_out;

    vq_all<<<MGRID, MBLK>>>((const float2*)ze, e, out);
}